// round 2
// baseline (speedup 1.0000x reference)
#include <cuda_runtime.h>

// AUGRU persistent kernel. B=2048 rows, T=200 steps, D=64.
// 128 CTAs x 16 rows, 128 threads. Weights + h-state resident in SMEM.

#define TT   200
#define DD   64
#define BC   16     // batch rows per CTA
#define PAD  20     // padded row stride (floats) for transposed activation tiles
#define NTHR 128

// SMEM layout (float offsets)
#define OFF_WG   0                      // W_gate   128*128
#define OFF_WC   16384                  // W_cand   128*64
#define OFF_BG   24576                  // b_gate   128
#define OFF_BC   24704                  // b_cand   64
#define OFF_ATT  24768                  // att      16*200
#define OFF_XT   27968                  // x tile   2 * 64 * PAD (double-buffered, transposed [d][r])
#define OFF_HT   (OFF_XT + 2*64*PAD)    // h        64 * PAD (transposed [j][r])
#define OFF_RHT  (OFF_HT + 64*PAD)      // r*h      64 * PAD
#define OFF_UT   (OFF_RHT + 64*PAD)     // u_att    64 * PAD
#define OFF_SL   (OFF_UT + 64*PAD)      // seqlen   16 (int)
#define SMEM_FLOATS (OFF_SL + 16)
#define SMEM_BYTES  (SMEM_FLOATS * 4)

__global__ void augru_zero_kernel(float* __restrict__ out, int n4) {
    int i = blockIdx.x * blockDim.x + threadIdx.x;
    if (i < n4) {
        ((float4*)out)[i] = make_float4(0.f, 0.f, 0.f, 0.f);
    }
}

__global__ void __launch_bounds__(NTHR, 1) augru_kernel(
    const float* __restrict__ x,       // [B, T, 64]
    const int*   __restrict__ seqlen,  // [B, 1]
    const float* __restrict__ att,     // [B, T, 1]
    const float* __restrict__ Wg,      // [128, 128]
    const float* __restrict__ bg,      // [128]
    const float* __restrict__ Wc,      // [128, 64]
    const float* __restrict__ bc,      // [64]
    float* __restrict__ out)           // [B, T, 64]
{
    extern __shared__ float sm[];
    const int tx   = threadIdx.x;
    const int row0 = blockIdx.x * BC;

    // ---------------- prologue: load weights / biases / att / seqlen ----------------
    for (int i = tx; i < 128 * 128; i += NTHR) sm[OFF_WG + i] = Wg[i];
    for (int i = tx; i < 128 * 64;  i += NTHR) sm[OFF_WC + i] = Wc[i];
    for (int i = tx; i < 128;       i += NTHR) sm[OFF_BG + i] = bg[i];
    for (int i = tx; i < 64;        i += NTHR) sm[OFF_BC + i] = bc[i];
    for (int i = tx; i < BC * TT;   i += NTHR) {
        int r = i / TT, t = i % TT;
        sm[OFF_ATT + i] = att[(size_t)(row0 + r) * TT + t];
    }
    for (int i = tx; i < 64 * PAD;  i += NTHR) sm[OFF_HT + i] = 0.f;
    if (tx < BC) ((int*)(sm + OFF_SL))[tx] = seqlen[row0 + tx];

    // ---------------- preload x(t=0) into xT buffer 0 (transposed) ----------------
    const int rx = tx >> 3;            // 0..15 (row)
    const int d0 = (tx & 7) * 8;       // 0,8,..,56
    const float* xpf = x + ((size_t)(row0 + rx) * TT) * DD + d0;   // prefetch base
    {
        float4 p0 = *(const float4*)xpf;
        float4 p1 = *(const float4*)(xpf + 4);
        float* xw = sm + OFF_XT;       // buffer 0
        xw[(d0 + 0) * PAD + rx] = p0.x;
        xw[(d0 + 1) * PAD + rx] = p0.y;
        xw[(d0 + 2) * PAD + rx] = p0.z;
        xw[(d0 + 3) * PAD + rx] = p0.w;
        xw[(d0 + 4) * PAD + rx] = p1.x;
        xw[(d0 + 5) * PAD + rx] = p1.y;
        xw[(d0 + 6) * PAD + rx] = p1.z;
        xw[(d0 + 7) * PAD + rx] = p1.w;
    }
    __syncthreads();

    const int* sl = (const int*)(sm + OFF_SL);
    int ml = 0;
    #pragma unroll
    for (int i = 0; i < BC; i++) ml = max(ml, sl[i]);

    // gates thread tiling: 32 col-groups x 4 row-groups -> 4 cols x 4 rows each
    const int gj0 = (tx & 31) * 4;     // gate column base (0..124)
    const int gr0 = (tx >> 5) * 4;     // row base (0,4,8,12)
    // cand  thread tiling: 16 col-groups x 8 row-groups -> 4 cols x 2 rows each
    const int cj0 = (tx & 15) * 4;     // cand column base (0..60)
    const int cr0 = (tx >> 4) * 2;     // row base (0,2,..,14)

    for (int t = 0; t < ml; ++t) {
        const float* xb = sm + OFF_XT + (t & 1) * 64 * PAD;

        // prefetch next x tile into registers (lands during gates GEMM)
        float4 q0, q1;
        const bool pf = (t + 1 < ml);
        if (pf) {
            const float* s2 = xpf + (size_t)(t + 1) * DD;
            q0 = *(const float4*)s2;
            q1 = *(const float4*)(s2 + 4);
        }

        // ---------------- gates GEMM: [16 x 128] = [16 x 128(x,h)] @ Wg ----------------
        float a[4][4];
        #pragma unroll
        for (int i = 0; i < 4; i++)
            #pragma unroll
            for (int j = 0; j < 4; j++) a[i][j] = 0.f;

        #pragma unroll 16
        for (int k = 0; k < 64; k++) {
            float4 w = *(const float4*)(sm + OFF_WG + k * 128 + gj0);
            float4 v = *(const float4*)(xb + k * PAD + gr0);
            float vv[4] = {v.x, v.y, v.z, v.w};
            float ww[4] = {w.x, w.y, w.z, w.w};
            #pragma unroll
            for (int i = 0; i < 4; i++)
                #pragma unroll
                for (int j = 0; j < 4; j++) a[i][j] += vv[i] * ww[j];
        }
        #pragma unroll 16
        for (int k = 0; k < 64; k++) {
            float4 w = *(const float4*)(sm + OFF_WG + (k + 64) * 128 + gj0);
            float4 v = *(const float4*)(sm + OFF_HT + k * PAD + gr0);
            float vv[4] = {v.x, v.y, v.z, v.w};
            float ww[4] = {w.x, w.y, w.z, w.w};
            #pragma unroll
            for (int i = 0; i < 4; i++)
                #pragma unroll
                for (int j = 0; j < 4; j++) a[i][j] += vv[i] * ww[j];
        }

        // sigmoid + scatter: r-gates -> r*h, u-gates -> att*u
        if (gj0 < 64) {
            #pragma unroll
            for (int j = 0; j < 4; j++) {
                float bgi = sm[OFF_BG + gj0 + j];
                #pragma unroll
                for (int i = 0; i < 4; i++) {
                    float g = a[i][j] + bgi;
                    float s = 1.f / (1.f + __expf(-g));
                    float h = sm[OFF_HT + (gj0 + j) * PAD + gr0 + i];
                    sm[OFF_RHT + (gj0 + j) * PAD + gr0 + i] = s * h;
                }
            }
        } else {
            #pragma unroll
            for (int j = 0; j < 4; j++) {
                float bgi = sm[OFF_BG + gj0 + j];
                #pragma unroll
                for (int i = 0; i < 4; i++) {
                    float g  = a[i][j] + bgi;
                    float u  = 1.f / (1.f + __expf(-g));
                    float ua = u * sm[OFF_ATT + (gr0 + i) * TT + t];
                    sm[OFF_UT + (gj0 - 64 + j) * PAD + gr0 + i] = ua;
                }
            }
        }
        __syncthreads();

        // ---------------- cand GEMM: [16 x 64] = [16 x 128(x, r*h)] @ Wc ----------------
        float c2[2][4];
        #pragma unroll
        for (int i = 0; i < 2; i++)
            #pragma unroll
            for (int j = 0; j < 4; j++) c2[i][j] = 0.f;

        #pragma unroll 16
        for (int k = 0; k < 64; k++) {
            float4 w = *(const float4*)(sm + OFF_WC + k * 64 + cj0);
            float v0 = xb[k * PAD + cr0];
            float v1 = xb[k * PAD + cr0 + 1];
            float ww[4] = {w.x, w.y, w.z, w.w};
            #pragma unroll
            for (int j = 0; j < 4; j++) { c2[0][j] += v0 * ww[j]; c2[1][j] += v1 * ww[j]; }
        }
        #pragma unroll 16
        for (int k = 0; k < 64; k++) {
            float4 w = *(const float4*)(sm + OFF_WC + (k + 64) * 64 + cj0);
            float v0 = sm[OFF_RHT + k * PAD + cr0];
            float v1 = sm[OFF_RHT + k * PAD + cr0 + 1];
            float ww[4] = {w.x, w.y, w.z, w.w};
            #pragma unroll
            for (int j = 0; j < 4; j++) { c2[0][j] += v0 * ww[j]; c2[1][j] += v1 * ww[j]; }
        }

        // tanh + AUGRU update + masked state/output writes
        #pragma unroll
        for (int i = 0; i < 2; i++) {
            const int r = cr0 + i;
            const bool valid = (t < sl[r]);
            float o[4];
            #pragma unroll
            for (int j = 0; j < 4; j++) {
                float cv = tanhf(c2[i][j] + sm[OFF_BC + cj0 + j]);
                float h  = sm[OFF_HT + (cj0 + j) * PAD + r];
                float ua = sm[OFF_UT + (cj0 + j) * PAD + r];
                float hn = (1.f - ua) * h + ua * cv;
                o[j] = hn;
                if (valid) sm[OFF_HT + (cj0 + j) * PAD + r] = hn;
            }
            if (valid) {
                float4 o4 = make_float4(o[0], o[1], o[2], o[3]);
                *(float4*)(out + ((size_t)(row0 + r) * TT + t) * DD + cj0) = o4;
            }
        }

        // store prefetched x into the other buffer (read after the sync below)
        if (pf) {
            float* xw = sm + OFF_XT + ((t + 1) & 1) * 64 * PAD;
            xw[(d0 + 0) * PAD + rx] = q0.x;
            xw[(d0 + 1) * PAD + rx] = q0.y;
            xw[(d0 + 2) * PAD + rx] = q0.z;
            xw[(d0 + 3) * PAD + rx] = q0.w;
            xw[(d0 + 4) * PAD + rx] = q1.x;
            xw[(d0 + 5) * PAD + rx] = q1.y;
            xw[(d0 + 6) * PAD + rx] = q1.z;
            xw[(d0 + 7) * PAD + rx] = q1.w;
        }
        __syncthreads();
    }
}

extern "C" void kernel_launch(void* const* d_in, const int* in_sizes, int n_in,
                              void* d_out, int out_size) {
    const float* x      = (const float*)d_in[0];
    const int*   seqlen = (const int*)  d_in[1];
    const float* att    = (const float*)d_in[2];
    const float* Wg     = (const float*)d_in[3];
    const float* bg     = (const float*)d_in[4];
    const float* Wc     = (const float*)d_in[5];
    const float* bc     = (const float*)d_in[6];
    float* out = (float*)d_out;

    const int B = in_sizes[0] / (TT * DD);   // 2048

    // zero the output (positions past seq_len must be exactly 0)
    {
        int n4 = out_size / 4;
        int blk = 256;
        int grd = (n4 + blk - 1) / blk;
        augru_zero_kernel<<<grd, blk>>>(out, n4);
    }

    cudaFuncSetAttribute(augru_kernel, cudaFuncAttributeMaxDynamicSharedMemorySize, SMEM_BYTES);
    augru_kernel<<<B / BC, NTHR, SMEM_BYTES>>>(x, seqlen, att, Wg, bg, Wc, bc, out);
}

// round 5
// speedup vs baseline: 1.1754x; 1.1754x over previous
#include <cuda_runtime.h>

// AUGRU persistent kernel. B=2048 rows, T=200 steps, D=64.
// 128 CTAs x 16 rows, 256 threads (2 warps per SMSP for latency hiding).
// Weights + h-state resident in SMEM.

#define TT   200
#define DD   64
#define BC   16     // batch rows per CTA
#define PAD  20     // padded row stride (floats) for transposed activation tiles
#define NTHR 256

// SMEM layout (float offsets)
#define OFF_WG   0                      // W_gate   128*128
#define OFF_WC   16384                  // W_cand   128*64
#define OFF_BG   24576                  // b_gate   128
#define OFF_BC   24704                  // b_cand   64
#define OFF_ATT  24768                  // att      16*200
#define OFF_XT   27968                  // x tile   2 * 64 * PAD (double-buffered, transposed [d][r])
#define OFF_HT   (OFF_XT + 2*64*PAD)    // h        64 * PAD (transposed [j][r])
#define OFF_RHT  (OFF_HT + 64*PAD)      // r*h      64 * PAD
#define OFF_UT   (OFF_RHT + 64*PAD)     // u_att    64 * PAD
#define OFF_SL   (OFF_UT + 64*PAD)      // seqlen   16 (int)
#define SMEM_FLOATS (OFF_SL + 16)
#define SMEM_BYTES  (SMEM_FLOATS * 4)

__global__ void augru_zero_kernel(float* __restrict__ out, int n4) {
    int i = blockIdx.x * blockDim.x + threadIdx.x;
    if (i < n4) {
        ((float4*)out)[i] = make_float4(0.f, 0.f, 0.f, 0.f);
    }
}

__global__ void __launch_bounds__(NTHR, 1) augru_kernel(
    const float* __restrict__ x,       // [B, T, 64]
    const int*   __restrict__ seqlen,  // [B, 1]
    const float* __restrict__ att,     // [B, T, 1]
    const float* __restrict__ Wg,      // [128, 128]
    const float* __restrict__ bg,      // [128]
    const float* __restrict__ Wc,      // [128, 64]
    const float* __restrict__ bc,      // [64]
    float* __restrict__ out)           // [B, T, 64]
{
    extern __shared__ float sm[];
    const int tx   = threadIdx.x;
    const int row0 = blockIdx.x * BC;

    // ---------------- prologue: load weights / biases / att / seqlen ----------------
    for (int i = tx; i < 128 * 128; i += NTHR) sm[OFF_WG + i] = Wg[i];
    for (int i = tx; i < 128 * 64;  i += NTHR) sm[OFF_WC + i] = Wc[i];
    for (int i = tx; i < 128;       i += NTHR) sm[OFF_BG + i] = bg[i];
    for (int i = tx; i < 64;        i += NTHR) sm[OFF_BC + i] = bc[i];
    for (int i = tx; i < BC * TT;   i += NTHR) {
        int r = i / TT, t = i % TT;
        sm[OFF_ATT + i] = att[(size_t)(row0 + r) * TT + t];
    }
    for (int i = tx; i < 64 * PAD;  i += NTHR) sm[OFF_HT + i] = 0.f;
    if (tx < BC) ((int*)(sm + OFF_SL))[tx] = seqlen[row0 + tx];

    // ---------------- preload x(t=0) into xT buffer 0 (transposed) ----------------
    const int rx = tx >> 4;            // 0..15 (row)
    const int d0 = (tx & 15) * 4;      // 0,4,..,60
    const float* xpf = x + ((size_t)(row0 + rx) * TT) * DD + d0;   // prefetch base
    {
        float4 p = *(const float4*)xpf;
        float* xw = sm + OFF_XT;       // buffer 0
        xw[(d0 + 0) * PAD + rx] = p.x;
        xw[(d0 + 1) * PAD + rx] = p.y;
        xw[(d0 + 2) * PAD + rx] = p.z;
        xw[(d0 + 3) * PAD + rx] = p.w;
    }
    __syncthreads();

    const int* sl = (const int*)(sm + OFF_SL);
    int ml = 0;
    #pragma unroll
    for (int i = 0; i < BC; i++) ml = max(ml, sl[i]);

    // gates tiling: each thread owns 1 column x 8 rows
    const int gj  = tx & 127;          // gate column 0..127
    const int gr8 = (tx >> 7) * 8;     // row base: 0 or 8
    // cand tiling: each thread owns 1 column x 4 rows
    const int cj  = tx & 63;           // cand column 0..63
    const int cr4 = (tx >> 6) * 4;     // row base: 0,4,8,12

    const float* wgcol = sm + OFF_WG + gj;
    const float* wccol = sm + OFF_WC + cj;

    for (int t = 0; t < ml; ++t) {
        const float* xb = sm + OFF_XT + (t & 1) * 64 * PAD;

        // prefetch next x tile into registers (lands during gates GEMM)
        float4 q;
        const bool pf = (t + 1 < ml);
        if (pf) {
            q = *(const float4*)(xpf + (size_t)(t + 1) * DD);
        }

        // ---------------- gates GEMM: [16 x 128] = [16 x 128(x,h)] @ Wg ----------------
        float a0 = 0.f, a1 = 0.f, a2 = 0.f, a3 = 0.f;
        float a4 = 0.f, a5 = 0.f, a6 = 0.f, a7 = 0.f;

        #pragma unroll 8
        for (int k = 0; k < 64; k++) {
            float  w  = wgcol[k * 128];
            float4 v0 = *(const float4*)(xb + k * PAD + gr8);
            float4 v1 = *(const float4*)(xb + k * PAD + gr8 + 4);
            a0 += v0.x * w; a1 += v0.y * w; a2 += v0.z * w; a3 += v0.w * w;
            a4 += v1.x * w; a5 += v1.y * w; a6 += v1.z * w; a7 += v1.w * w;
        }
        #pragma unroll 8
        for (int k = 0; k < 64; k++) {
            float  w  = wgcol[(k + 64) * 128];
            float4 v0 = *(const float4*)(sm + OFF_HT + k * PAD + gr8);
            float4 v1 = *(const float4*)(sm + OFF_HT + k * PAD + gr8 + 4);
            a0 += v0.x * w; a1 += v0.y * w; a2 += v0.z * w; a3 += v0.w * w;
            a4 += v1.x * w; a5 += v1.y * w; a6 += v1.z * w; a7 += v1.w * w;
        }

        // sigmoid + scatter: r-gates -> r*h, u-gates -> att*u
        {
            const float bgi = sm[OFF_BG + gj];
            float g[8] = {a0, a1, a2, a3, a4, a5, a6, a7};
            float s[8];
            #pragma unroll
            for (int i = 0; i < 8; i++)
                s[i] = 1.f / (1.f + __expf(-(g[i] + bgi)));

            if (gj < 64) {
                float4 h0 = *(const float4*)(sm + OFF_HT + gj * PAD + gr8);
                float4 h1 = *(const float4*)(sm + OFF_HT + gj * PAD + gr8 + 4);
                float4 o0 = make_float4(s[0] * h0.x, s[1] * h0.y, s[2] * h0.z, s[3] * h0.w);
                float4 o1 = make_float4(s[4] * h1.x, s[5] * h1.y, s[6] * h1.z, s[7] * h1.w);
                *(float4*)(sm + OFF_RHT + gj * PAD + gr8)     = o0;
                *(float4*)(sm + OFF_RHT + gj * PAD + gr8 + 4) = o1;
            } else {
                const int uj = gj - 64;
                float4 o0, o1;
                o0.x = s[0] * sm[OFF_ATT + (gr8 + 0) * TT + t];
                o0.y = s[1] * sm[OFF_ATT + (gr8 + 1) * TT + t];
                o0.z = s[2] * sm[OFF_ATT + (gr8 + 2) * TT + t];
                o0.w = s[3] * sm[OFF_ATT + (gr8 + 3) * TT + t];
                o1.x = s[4] * sm[OFF_ATT + (gr8 + 4) * TT + t];
                o1.y = s[5] * sm[OFF_ATT + (gr8 + 5) * TT + t];
                o1.z = s[6] * sm[OFF_ATT + (gr8 + 6) * TT + t];
                o1.w = s[7] * sm[OFF_ATT + (gr8 + 7) * TT + t];
                *(float4*)(sm + OFF_UT + uj * PAD + gr8)     = o0;
                *(float4*)(sm + OFF_UT + uj * PAD + gr8 + 4) = o1;
            }
        }
        __syncthreads();

        // ---------------- cand GEMM: [16 x 64] = [16 x 128(x, r*h)] @ Wc ----------------
        float c0 = 0.f, c1 = 0.f, c2 = 0.f, c3 = 0.f;

        #pragma unroll 8
        for (int k = 0; k < 64; k++) {
            float  w = wccol[k * 64];
            float4 v = *(const float4*)(xb + k * PAD + cr4);
            c0 += v.x * w; c1 += v.y * w; c2 += v.z * w; c3 += v.w * w;
        }
        #pragma unroll 8
        for (int k = 0; k < 64; k++) {
            float  w = wccol[(k + 64) * 64];
            float4 v = *(const float4*)(sm + OFF_RHT + k * PAD + cr4);
            c0 += v.x * w; c1 += v.y * w; c2 += v.z * w; c3 += v.w * w;
        }

        // tanh + AUGRU update + masked state/output (masks folded into values)
        {
            const float bcj = sm[OFF_BC + cj];
            float4 hv = *(const float4*)(sm + OFF_HT + cj * PAD + cr4);
            float4 ua = *(const float4*)(sm + OFF_UT + cj * PAD + cr4);
            float cc[4] = {c0, c1, c2, c3};
            float hh[4] = {hv.x, hv.y, hv.z, hv.w};
            float uu[4] = {ua.x, ua.y, ua.z, ua.w};
            float hs[4], os[4];
            #pragma unroll
            for (int i = 0; i < 4; i++) {
                float cv = tanhf(cc[i] + bcj);
                float hn = (1.f - uu[i]) * hh[i] + uu[i] * cv;
                bool valid = (t < sl[cr4 + i]);
                hs[i] = valid ? hn : hh[i];
                os[i] = valid ? hn : 0.f;
            }
            *(float4*)(sm + OFF_HT + cj * PAD + cr4) =
                make_float4(hs[0], hs[1], hs[2], hs[3]);
            #pragma unroll
            for (int i = 0; i < 4; i++) {
                out[((size_t)(row0 + cr4 + i) * TT + t) * DD + cj] = os[i];
            }
        }

        // store prefetched x into the other buffer (read after the sync below)
        if (pf) {
            float* xw = sm + OFF_XT + ((t + 1) & 1) * 64 * PAD;
            xw[(d0 + 0) * PAD + rx] = q.x;
            xw[(d0 + 1) * PAD + rx] = q.y;
            xw[(d0 + 2) * PAD + rx] = q.z;
            xw[(d0 + 3) * PAD + rx] = q.w;
        }
        __syncthreads();
    }
}

extern "C" void kernel_launch(void* const* d_in, const int* in_sizes, int n_in,
                              void* d_out, int out_size) {
    const float* x      = (const float*)d_in[0];
    const int*   seqlen = (const int*)  d_in[1];
    const float* att    = (const float*)d_in[2];
    const float* Wg     = (const float*)d_in[3];
    const float* bg     = (const float*)d_in[4];
    const float* Wc     = (const float*)d_in[5];
    const float* bc     = (const float*)d_in[6];
    float* out = (float*)d_out;

    const int B = in_sizes[0] / (TT * DD);   // 2048

    // zero the output (positions past seq_len must be exactly 0)
    {
        int n4 = out_size / 4;
        int blk = 256;
        int grd = (n4 + blk - 1) / blk;
        augru_zero_kernel<<<grd, blk>>>(out, n4);
    }

    cudaFuncSetAttribute(augru_kernel, cudaFuncAttributeMaxDynamicSharedMemorySize, SMEM_BYTES);
    augru_kernel<<<B / BC, NTHR, SMEM_BYTES>>>(x, seqlen, att, Wg, bg, Wc, bc, out);
}